// round 8
// baseline (speedup 1.0000x reference)
#include <cuda_runtime.h>
#include <cstdint>

#define B_    64
#define S_    2048
#define H_    1024
#define SPLIT 16
#define CHUNK (S_ / SPLIT)      // 128 timesteps per CTA
#define TILE  4
#define NTILES (CHUNK / TILE)   // 32
#define THREADS 256             // one float4 column slice per thread
#define WARPS (THREADS / 32)

// Scratch (allocation-free: __device__ globals)
__device__ float g_expE [B_ * S_];             // exp(tanh(score)) per (b,s)
__device__ float g_partL[B_ * SPLIT];          // partial sum of exp per chunk
__device__ float g_partC[B_ * SPLIT * H_];     // partial context per chunk (4 MiB)

// ---------------------------------------------------------------------------
// Pass 1: single DRAM read of rnn_output.
// Thread t owns H columns [4t,4t+4). Per tile of 4 timesteps (TILE=4 keeps
// regs ~50 so 5 CTAs/SM fit -> more independently-phased CTAs hide each
// other's reduce windows):
//   1. front-batched float4 loads (MLP=4)  2. partial dots vs w4
//   3. full warp-reduce (lane 0)  4. lane0 -> ping-pong red[p]
//   5. ONE __syncthreads  6. every warp redundantly finishes: lanes 0-3 sum
//      the 8 per-warp values, t=exp(tanh(.)), broadcast via shuffle
//   7. acc += t*xr from registers.
// tanh in [-1,1] -> softmax needs no max subtraction.
// ---------------------------------------------------------------------------
__global__ __launch_bounds__(THREADS, 5)
void pass1_kernel(const float* __restrict__ x,
                  const float* __restrict__ w,
                  const float* __restrict__ bptr)
{
    __shared__ float red[2][WARPS * TILE];   // ping-pong per-warp dot partials
    __shared__ float lred[TILE];

    const int b     = blockIdx.x / SPLIT;
    const int chunk = blockIdx.x % SPLIT;
    const int tid   = threadIdx.x;
    const int warp  = tid >> 5;
    const int lane  = tid & 31;
    const float bias = __ldg(bptr);
    const float4 w4 = reinterpret_cast<const float4*>(w)[tid];

    float4 acc = make_float4(0.f, 0.f, 0.f, 0.f);
    float lsum = 0.f;                        // warp 0, lanes 0-3 accumulate

    const int s0 = chunk * CHUNK;
    const float4* xp0 = reinterpret_cast<const float4*>(x) +
                        ((size_t)b * S_ + s0) * (H_ / 4) + tid;

    #pragma unroll 1
    for (int tile = 0; tile < NTILES; tile++) {
        const float4* xp = xp0 + (size_t)tile * TILE * (H_ / 4);
        const int p = tile & 1;

        // 1. front-batched loads
        float4 xr[TILE];
        #pragma unroll
        for (int s = 0; s < TILE; s++)
            xr[s] = xp[(size_t)s * (H_ / 4)];

        // 2. partial dots
        float d[TILE];
        #pragma unroll
        for (int s = 0; s < TILE; s++)
            d[s] = xr[s].x * w4.x + xr[s].y * w4.y
                 + xr[s].z * w4.z + xr[s].w * w4.w;

        // 3. full warp reduce (lane 0 holds result)
        #pragma unroll
        for (int s = 0; s < TILE; s++) {
            #pragma unroll
            for (int off = 16; off; off >>= 1)
                d[s] += __shfl_xor_sync(0xffffffffu, d[s], off);
        }

        // 4. lane 0 publishes per-warp partials
        if (lane == 0) {
            #pragma unroll
            for (int s = 0; s < TILE; s++)
                red[p][warp * TILE + s] = d[s];
        }

        // 5. single barrier per tile (ping-pong makes this sufficient)
        __syncthreads();

        // 6. redundant finish in every warp: lanes 0-3 own one timestep each
        float t = 0.f;
        if (lane < TILE) {
            float v = 0.f;
            #pragma unroll
            for (int j = 0; j < WARPS; j++)
                v += red[p][j * TILE + lane];
            t = __expf(tanhf(v + bias));
            if (warp == 0) {
                g_expE[(size_t)b * S_ + s0 + tile * TILE + lane] = t;
                lsum += t;
            }
        }

        // 7. broadcast t and accumulate from registers
        #pragma unroll
        for (int s = 0; s < TILE; s++) {
            const float ts = __shfl_sync(0xffffffffu, t, s);
            acc.x += ts * xr[s].x;
            acc.y += ts * xr[s].y;
            acc.z += ts * xr[s].z;
            acc.w += ts * xr[s].w;
        }
    }

    // write partial context (each thread owns its own float4 slot)
    reinterpret_cast<float4*>(
        g_partC + ((size_t)b * SPLIT + chunk) * H_)[tid] = acc;

    // combine warp-0 lane lsums
    if (warp == 0 && lane < TILE) lred[lane] = lsum;
    __syncthreads();
    if (tid == 0) {
        float l = 0.f;
        #pragma unroll
        for (int i = 0; i < TILE; i++) l += lred[i];
        g_partL[b * SPLIT + chunk] = l;
    }
}

// ---------------------------------------------------------------------------
// Finish (fused linv + outputs). One batch per block:
//   blocks [0,64):   context block for b = blockIdx  (H/4 = 256 = blockDim)
//   blocks [64,192): weight blocks, 2 per batch (S/4 = 512 = 2*blockDim)
// Warp 0 reduces the 16 partL values -> s_inv (no separate linv kernel).
// ---------------------------------------------------------------------------
__global__ __launch_bounds__(THREADS)
void finish_kernel(float* __restrict__ ctx_out, float* __restrict__ wts_out)
{
    const int blk = blockIdx.x;
    const int tid = threadIdx.x;
    const bool is_ctx = (blk < B_);
    const int b = is_ctx ? blk : ((blk - B_) >> 1);

    __shared__ float s_inv;
    if (tid < 32) {
        float l = (tid < SPLIT) ? g_partL[b * SPLIT + tid] : 0.f;
        #pragma unroll
        for (int off = 16; off; off >>= 1)
            l += __shfl_xor_sync(0xffffffffu, l, off);
        if (tid == 0) s_inv = 1.f / l;
    }
    __syncthreads();
    const float inv = s_inv;

    if (is_ctx) {
        float4 acc = make_float4(0.f, 0.f, 0.f, 0.f);
        #pragma unroll
        for (int c = 0; c < SPLIT; c++) {          // 16 independent loads
            float4 v = reinterpret_cast<const float4*>(
                g_partC + ((size_t)b * SPLIT + c) * H_)[tid];
            acc.x += v.x; acc.y += v.y; acc.z += v.z; acc.w += v.w;
        }
        acc.x *= inv; acc.y *= inv; acc.z *= inv; acc.w *= inv;
        reinterpret_cast<float4*>(ctx_out)[b * (H_ / 4) + tid] = acc;
    } else {
        const int half = (blk - B_) & 1;
        const int idx  = b * (S_ / 4) + half * THREADS + tid;
        float4 e = reinterpret_cast<const float4*>(g_expE)[idx];
        e.x *= inv; e.y *= inv; e.z *= inv; e.w *= inv;
        reinterpret_cast<float4*>(wts_out)[idx] = e;
    }
}

extern "C" void kernel_launch(void* const* d_in, const int* in_sizes, int n_in,
                              void* d_out, int out_size)
{
    const float* x    = (const float*)d_in[0];   // rnn_output [B,S,H]
    const float* w    = (const float*)d_in[1];   // attn_w [H]
    const float* bptr = (const float*)d_in[2];   // attn_b scalar

    float* out = (float*)d_out;                  // context [B,H] then weights [B,S]
    float* ctx_out = out;
    float* wts_out = out + (size_t)B_ * H_;

    pass1_kernel<<<B_ * SPLIT, THREADS>>>(x, w, bptr);
    finish_kernel<<<B_ * 3, THREADS>>>(ctx_out, wts_out);
}

// round 9
// speedup vs baseline: 1.1948x; 1.1948x over previous
#include <cuda_runtime.h>
#include <cstdint>

#define B_    64
#define S_    2048
#define H_    1024
#define SPLIT 16
#define CHUNK (S_ / SPLIT)      // 128 timesteps per CTA
#define TILE  8
#define NTILES (CHUNK / TILE)   // 16
#define THREADS 256             // one float4 column slice per thread
#define WARPS (THREADS / 32)

// Scratch (allocation-free: __device__ globals)
__device__ float g_expE [B_ * S_];             // exp(tanh(score)) per (b,s)
__device__ float g_partL[B_ * SPLIT];          // partial sum of exp per chunk
__device__ float g_partC[B_ * SPLIT * H_];     // partial context per chunk (4 MiB)
__device__ int   g_count[B_];                  // arrival counter per batch
                                               // (zero-init; finisher resets)

// ---------------------------------------------------------------------------
// Fused kernel: single DRAM read of rnn_output + finisher-CTA epilogue.
// Main phase (per CTA = one (batch, chunk of 128 timesteps)):
//   Thread t owns H columns [4t,4t+4). Per tile of 8 timesteps:
//   1. front-batched float4 loads (MLP=8)  2. partial dots vs w4 (registers)
//   3. full warp-reduce (lane 0)  4. lane0 -> ping-pong red[p]
//   5. ONE __syncthreads  6. every warp redundantly finishes: lanes 0-7 sum
//      the 8 per-warp values, t=exp(tanh(.)), broadcast via shuffle
//   7. acc += t*xr from registers.
//   tanh in [-1,1] -> softmax needs no max subtraction.
// Epilogue (threadfence-reduction): flush (partC, partL), __threadfence,
// atomicAdd(g_count[b]); the 16th arrival becomes the finisher: reduces the
// 16 partL -> inv, sums 16 context partials -> context[b], and writes
// weights[b,:] = expE * inv. Finisher resets the counter (deterministic,
// graph-replayable). All float math in fixed order.
// ---------------------------------------------------------------------------
__global__ __launch_bounds__(THREADS, 4)
void fused_kernel(const float* __restrict__ x,
                  const float* __restrict__ w,
                  const float* __restrict__ bptr,
                  float* __restrict__ ctx_out,
                  float* __restrict__ wts_out)
{
    __shared__ float red[2][WARPS * TILE];   // ping-pong per-warp dot partials
    __shared__ float lred[TILE];
    __shared__ int   s_last;
    __shared__ float s_inv;

    const int b     = blockIdx.x / SPLIT;
    const int chunk = blockIdx.x % SPLIT;
    const int tid   = threadIdx.x;
    const int warp  = tid >> 5;
    const int lane  = tid & 31;
    const float bias = __ldg(bptr);
    const float4 w4 = reinterpret_cast<const float4*>(w)[tid];

    float4 acc = make_float4(0.f, 0.f, 0.f, 0.f);
    float lsum = 0.f;                        // warp 0, lanes 0-7 accumulate

    const int s0 = chunk * CHUNK;
    const float4* xp0 = reinterpret_cast<const float4*>(x) +
                        ((size_t)b * S_ + s0) * (H_ / 4) + tid;

    #pragma unroll 1
    for (int tile = 0; tile < NTILES; tile++) {
        const float4* xp = xp0 + (size_t)tile * TILE * (H_ / 4);
        const int p = tile & 1;

        // 1. front-batched loads
        float4 xr[TILE];
        #pragma unroll
        for (int s = 0; s < TILE; s++)
            xr[s] = xp[(size_t)s * (H_ / 4)];

        // 2. partial dots
        float d[TILE];
        #pragma unroll
        for (int s = 0; s < TILE; s++)
            d[s] = xr[s].x * w4.x + xr[s].y * w4.y
                 + xr[s].z * w4.z + xr[s].w * w4.w;

        // 3. full warp reduce (lane 0 holds result)
        #pragma unroll
        for (int s = 0; s < TILE; s++) {
            #pragma unroll
            for (int off = 16; off; off >>= 1)
                d[s] += __shfl_xor_sync(0xffffffffu, d[s], off);
        }

        // 4. lane 0 publishes 8 per-warp partials
        if (lane == 0) {
            #pragma unroll
            for (int s = 0; s < TILE; s++)
                red[p][warp * TILE + s] = d[s];
        }

        // 5. single barrier per tile (ping-pong makes this sufficient)
        __syncthreads();

        // 6. redundant finish in every warp: lanes 0-7 own one timestep each
        float t = 0.f;
        if (lane < TILE) {
            float v = 0.f;
            #pragma unroll
            for (int j = 0; j < WARPS; j++)
                v += red[p][j * TILE + lane];
            t = __expf(tanhf(v + bias));
            if (warp == 0) {
                g_expE[(size_t)b * S_ + s0 + tile * TILE + lane] = t;
                lsum += t;
            }
        }

        // 7. broadcast t and accumulate from registers
        #pragma unroll
        for (int s = 0; s < TILE; s++) {
            const float ts = __shfl_sync(0xffffffffu, t, s);
            acc.x += ts * xr[s].x;
            acc.y += ts * xr[s].y;
            acc.z += ts * xr[s].z;
            acc.w += ts * xr[s].w;
        }
    }

    // flush partial context (each thread owns its own float4 slot)
    reinterpret_cast<float4*>(
        g_partC + ((size_t)b * SPLIT + chunk) * H_)[tid] = acc;

    // combine warp-0 lane lsums -> partL
    if (warp == 0 && lane < TILE) lred[lane] = lsum;
    __syncthreads();
    if (tid == 0) {
        float l = 0.f;
        #pragma unroll
        for (int i = 0; i < TILE; i++) l += lred[i];
        g_partL[b * SPLIT + chunk] = l;
    }

    // -------- finisher election (threadfence reduction pattern) --------
    __threadfence();                 // make this CTA's flush globally visible
    __syncthreads();                 // incl. tid0's partL store before fence?
                                     // (tid0 stored before its own fence: OK)
    if (tid == 0) {
        const int old = atomicAdd(&g_count[b], 1);
        s_last = (old == SPLIT - 1);
        if (s_last) g_count[b] = 0;  // reset for next graph replay (safe:
                                     // all SPLIT arrivals already happened)
    }
    __syncthreads();
    if (!s_last) return;
    __threadfence();                 // acquire side: see peers' flushes

    // -------- epilogue: this CTA finishes batch b --------
    if (tid < 32) {
        float l = (tid < SPLIT) ? g_partL[b * SPLIT + tid] : 0.f;
        #pragma unroll
        for (int off = 16; off; off >>= 1)
            l += __shfl_xor_sync(0xffffffffu, l, off);
        if (tid == 0) s_inv = 1.f / l;
    }
    __syncthreads();
    const float inv = s_inv;

    // context[b][:] : 256 threads x one float4, 16 independent partial loads
    float4 c = make_float4(0.f, 0.f, 0.f, 0.f);
    #pragma unroll
    for (int cc = 0; cc < SPLIT; cc++) {
        float4 v = reinterpret_cast<const float4*>(
            g_partC + ((size_t)b * SPLIT + cc) * H_)[tid];
        c.x += v.x; c.y += v.y; c.z += v.z; c.w += v.w;
    }
    c.x *= inv; c.y *= inv; c.z *= inv; c.w *= inv;
    reinterpret_cast<float4*>(ctx_out)[b * (H_ / 4) + tid] = c;

    // weights[b][:] : S/4 = 512 float4, 2 per thread
    #pragma unroll
    for (int i = 0; i < S_ / 4 / THREADS; i++) {
        const int idx = b * (S_ / 4) + i * THREADS + tid;
        float4 e = reinterpret_cast<const float4*>(g_expE)[idx];
        e.x *= inv; e.y *= inv; e.z *= inv; e.w *= inv;
        reinterpret_cast<float4*>(wts_out)[idx] = e;
    }
}

extern "C" void kernel_launch(void* const* d_in, const int* in_sizes, int n_in,
                              void* d_out, int out_size)
{
    const float* x    = (const float*)d_in[0];   // rnn_output [B,S,H]
    const float* w    = (const float*)d_in[1];   // attn_w [H]
    const float* bptr = (const float*)d_in[2];   // attn_b scalar

    float* out = (float*)d_out;                  // context [B,H] then weights [B,S]
    float* ctx_out = out;
    float* wts_out = out + (size_t)B_ * H_;

    fused_kernel<<<B_ * SPLIT, THREADS>>>(x, w, bptr, ctx_out, wts_out);
}